// round 16
// baseline (speedup 1.0000x reference)
#include <cuda_runtime.h>
#include <cuda_fp16.h>
#include <cstdint>

#define IN_CH   768
#define OUT_ROW 1536
#define BM      128
#define BN      128
#define NCHUNK  12          // 768/64
#define NT      1536        // tiles: 128 mtile * 4 ntile * 3 mod
#define GRID_P  444         // 148 SMs * 3 CTAs

// smem: [0,512) biasCur | [512,1024) biasNxt | [1024,1028) nextT |
//       [1040,1072) mbars full0 full1 empty0 empty1 | stages @2048
#define STGB     32768
#define SM_STG(s) (2048 + (s)*STGB)
#define OFF_B    16384
#define SMEM_TOTAL (2048 + 2*STGB)   // 67584 -> 3 CTAs/SM

#define SWZ(o) ((o) ^ (((o) >> 3) & 0x70))

// Pre-converted fp16 activations, SW128-swizzled, layout == smem A block:
// [mod 3][mtile 128][kchunk 12][128 rows][128 B]
__device__ __align__(128) unsigned char g_Ascr[3*128*12*16384];
// Pre-converted fp16 weights, layout == smem B block:
// [mod 3][ntile 4][kchunk 12][128 rows][128 B]
__device__ __align__(128) unsigned char g_Bscr[3*4*12*16384];
__device__ int g_ctr;    // work-stealing counter (reset by conv kernel)

static __device__ __forceinline__ uint32_t s2u(const void* p) {
    uint32_t a;
    asm("{ .reg .u64 t; cvta.to.shared.u64 t, %1; cvt.u32.u64 %0, t; }" : "=r"(a) : "l"(p));
    return a;
}
static __device__ __forceinline__ void ldsm4(uint32_t* r, uint32_t addr) {
    asm volatile("ldmatrix.sync.aligned.m8n8.x4.shared.b16 {%0,%1,%2,%3}, [%4];"
                 : "=r"(r[0]), "=r"(r[1]), "=r"(r[2]), "=r"(r[3]) : "r"(addr));
}
static __device__ __forceinline__ void mma16816(float* c, const uint32_t* a, const uint32_t* b) {
    asm volatile("mma.sync.aligned.m16n8k16.row.col.f32.f16.f16.f32 "
                 "{%0,%1,%2,%3}, {%4,%5,%6,%7}, {%8,%9}, {%0,%1,%2,%3};"
                 : "+f"(c[0]), "+f"(c[1]), "+f"(c[2]), "+f"(c[3])
                 : "r"(a[0]), "r"(a[1]), "r"(a[2]), "r"(a[3]), "r"(b[0]), "r"(b[1]));
}
static __device__ __forceinline__ void mbar_init(uint32_t a, uint32_t cnt) {
    asm volatile("mbarrier.init.shared.b64 [%0], %1;" :: "r"(a), "r"(cnt) : "memory");
}
static __device__ __forceinline__ void mbar_expect_tx(uint32_t a, uint32_t tx) {
    asm volatile("mbarrier.arrive.expect_tx.shared.b64 _, [%0], %1;" :: "r"(a), "r"(tx) : "memory");
}
static __device__ __forceinline__ void mbar_arrive(uint32_t a) {
    asm volatile("mbarrier.arrive.shared.b64 _, [%0];" :: "r"(a) : "memory");
}
static __device__ __forceinline__ void mbar_wait(uint32_t a, uint32_t parity) {
    asm volatile(
        "{\n\t.reg .pred P;\n"
        "W_%=:\n\t"
        "mbarrier.try_wait.parity.acquire.cta.shared::cta.b64 P, [%0], %1, 0x989680;\n\t"
        "@!P bra W_%=;\n\t}"
        :: "r"(a), "r"(parity) : "memory");
}
static __device__ __forceinline__ void bulk_g2s(uint32_t dst, const void* src,
                                                uint32_t bytes, uint32_t mbar) {
    asm volatile(
        "cp.async.bulk.shared::cluster.global.mbarrier::complete_tx::bytes [%0], [%1], %2, [%3];"
        :: "r"(dst), "l"(src), "r"(bytes), "r"(mbar) : "memory");
}

// ============ kernel 0: fused weight + activation conversion ============
__global__ __launch_bounds__(256)
void caps_conv(const float* __restrict__ x_img,
               const float* __restrict__ x_capt,
               const float* __restrict__ x_dct,
               const float* __restrict__ w_img,
               const float* __restrict__ w_capt,
               const float* __restrict__ w_dct)
{
    if (blockIdx.x == 0 && threadIdx.x == 0) g_ctr = GRID_P;

    if (blockIdx.x < 576) {
        int gt  = blockIdx.x * 256 + threadIdx.x;
        int mod = gt / 49152;
        int r   = gt % 49152;
        int n   = r / 96;
        int k8  = r % 96;
        const float* W = (mod == 0) ? w_img : (mod == 1) ? w_capt : w_dct;
        int wrow = ((n & 7) << 6) | (n >> 3);
        const float4* src = (const float4*)(W + (size_t)wrow * IN_CH + k8 * 8);
        float4 p = src[0], q = src[1];
        __half2 h0 = __float22half2_rn(make_float2(p.x, p.y));
        __half2 h1 = __float22half2_rn(make_float2(p.z, p.w));
        __half2 h2 = __float22half2_rn(make_float2(q.x, q.y));
        __half2 h3 = __float22half2_rn(make_float2(q.z, q.w));
        int ntile = n >> 7, rloc = n & 127;
        int kch = k8 >> 3, cell = k8 & 7;
        uint32_t off = SWZ((uint32_t)(rloc * 128 + cell * 16));
        unsigned char* dst = g_Bscr + (size_t)((mod * 4 + ntile) * 12 + kch) * 16384 + off;
        *(uint4*)dst = make_uint4(*(uint32_t*)&h0, *(uint32_t*)&h1, *(uint32_t*)&h2, *(uint32_t*)&h3);
    } else {
        int gt  = (blockIdx.x - 576) * 256 + threadIdx.x;
        int mod = gt / 1572864;
        int r   = gt % 1572864;
        int b   = r / 96;
        int k8  = r % 96;
        const float* X = (mod == 0) ? x_img : (mod == 1) ? x_capt : x_dct;
        const float4* src = (const float4*)(X + (size_t)b * IN_CH + k8 * 8);
        float4 p = src[0], q = src[1];
        __half2 h0 = __float22half2_rn(make_float2(p.x, p.y));
        __half2 h1 = __float22half2_rn(make_float2(p.z, p.w));
        __half2 h2 = __float22half2_rn(make_float2(q.x, q.y));
        __half2 h3 = __float22half2_rn(make_float2(q.z, q.w));
        int mtile = b >> 7, rloc = b & 127;
        int kch = k8 >> 3, cell = k8 & 7;
        uint32_t off = SWZ((uint32_t)(rloc * 128 + cell * 16));
        unsigned char* dst = g_Ascr + (size_t)(((mod * 128 + mtile) * 12) + kch) * 16384 + off;
        *(uint4*)dst = make_uint4(*(uint32_t*)&h0, *(uint32_t*)&h1, *(uint32_t*)&h2, *(uint32_t*)&h3);
    }
}

static __device__ __forceinline__ void decode_tile(int t,
    const unsigned char*& aG, const unsigned char*& bG, int& b0, int& n0, int& mod)
{
    mod = t / 512;
    int rem = t - mod * 512;
    int mtile = rem >> 2, ntile = rem & 3;
    aG = g_Ascr + (size_t)((mod * 128 + mtile) * 12) * 16384;
    bG = g_Bscr + (size_t)((mod * 4 + ntile) * 12) * 16384;
    b0 = mtile * BM;
    n0 = ntile * BN;
}

// ============ kernel 1: persistent GEMM, mbarrier/bulk-copy pipeline ============
__global__ __launch_bounds__(128, 3)
void caps_gemm(const float* __restrict__ b_img,
               const float* __restrict__ b_capt,
               const float* __restrict__ b_dct,
               float* __restrict__ out)
{
    extern __shared__ __align__(1024) unsigned char smem[];
    const uint32_t sb = s2u(smem);
    float* biasCur = (float*)smem;
    float* biasNxt = (float*)(smem + 512);
    volatile int* nextTS = (volatile int*)(smem + 1024);
    const uint32_t FULLB[2]  = { sb + 1040, sb + 1048 };
    const uint32_t EMPTB[2]  = { sb + 1056, sb + 1064 };

    const int tid  = threadIdx.x;
    const int lane = tid & 31;
    const int w    = tid >> 5;
    const int wm   = w & 1;
    const int wn   = w >> 1;

    const uint32_t aXor  = (uint32_t)((lane & 7) << 4);
    const uint32_t aRowB = (uint32_t)((wm * 64 + (lane & 15)) * 128);
    const uint32_t aCell = (uint32_t)(((lane >> 4) & 1) * 16);
    const uint32_t bXor  = aXor;
    const uint32_t bRowB = (uint32_t)((wn * 64 + (lane & 7) + ((lane & 16) ? 8 : 0)) * 128);
    const uint32_t bCell = (uint32_t)((lane & 8) ? 16 : 0);

    int t = blockIdx.x;
    const unsigned char *aG, *bG;
    int b0, n0, mod;
    decode_tile(t, aG, bG, b0, n0, mod);
    {
        const float* Bv = (mod == 0) ? b_img : (mod == 1) ? b_capt : b_dct;
        int n = n0 + tid; biasCur[tid] = Bv[((n & 7) << 6) + (n >> 3)];
    }
    if (tid == 0) {
        mbar_init(FULLB[0], 1); mbar_init(FULLB[1], 1);
        mbar_init(EMPTB[0], 4); mbar_init(EMPTB[1], 4);
    }
    __syncthreads();

    // prologue: fill stage 0 <- chunk 0, stage 1 <- chunk 1
    if (tid == 0) {
        mbar_expect_tx(FULLB[0], 32768);
        bulk_g2s(sb + SM_STG(0),         aG,         16384, FULLB[0]);
        bulk_g2s(sb + SM_STG(0) + OFF_B, bG,         16384, FULLB[0]);
        mbar_expect_tx(FULLB[1], 32768);
        bulk_g2s(sb + SM_STG(1),         aG + 16384, 16384, FULLB[1]);
        bulk_g2s(sb + SM_STG(1) + OFF_B, bG + 16384, 16384, FULLB[1]);
    }

    int gcons = 0;       // global stream chunk counter
    int nt0c  = NT;      // tid0's next-tile register

    for (;;) {
        float acc[4][8][4];
        #pragma unroll
        for (int i = 0; i < 4; ++i)
            #pragma unroll
            for (int j = 0; j < 8; ++j)
                #pragma unroll
                for (int k = 0; k < 4; ++k) acc[i][j][k] = 0.f;

        for (int i = 0; i < NCHUNK; ++i) {
            if (i == 0 && tid == 0) {
                int v = atomicAdd(&g_ctr, 1);
                nt0c = v;
                *nextTS = v;
            }
            const int s = gcons & 1;

            // consumer: wait stage full
            mbar_wait(FULLB[s], (uint32_t)((gcons >> 1) & 1));

            // compute chunk from stage s
            const uint32_t stg = sb + SM_STG(s);
            #pragma unroll
            for (int st = 0; st < 4; ++st) {
                const uint32_t sx = (uint32_t)(st << 5);
                uint32_t af[4][4];
                #pragma unroll
                for (int mt = 0; mt < 4; ++mt)
                    ldsm4(af[mt], stg + aRowB + mt * 2048 + ((sx + aCell) ^ aXor));
                #pragma unroll
                for (int g = 0; g < 4; ++g) {
                    uint32_t bf[4];
                    ldsm4(bf, stg + OFF_B + bRowB + g * 2048 + ((sx + bCell) ^ bXor));
                    #pragma unroll
                    for (int half = 0; half < 2; ++half) {
                        const uint32_t* BH = &bf[half * 2];
                        #pragma unroll
                        for (int mt = 0; mt < 4; ++mt)
                            mma16816(acc[mt][2 * g + half], af[mt], BH);
                    }
                }
            }

            // per-warp arrive: done reading stage s (MMAs force LDSM completion)
            if (lane == 0) mbar_arrive(EMPTB[s]);

            // producer (tid 0): fill stream chunk gcons+2 into stage s
            if (tid == 0) {
                const unsigned char *sa = nullptr, *sbp = nullptr;
                bool have = false;
                if (i < 10) {
                    sa  = aG + (size_t)(i + 2) * 16384;
                    sbp = bG + (size_t)(i + 2) * 16384;
                    have = true;
                } else if (nt0c < NT) {
                    const unsigned char *aN, *bN; int d0, d1, d2;
                    decode_tile(nt0c, aN, bN, d0, d1, d2);
                    sa  = aN + (size_t)(i - 10) * 16384;
                    sbp = bN + (size_t)(i - 10) * 16384;
                    have = true;
                }
                if (have) {
                    int f = (gcons + 2) >> 1;                    // per-stage fill index (>=1)
                    mbar_wait(EMPTB[s], (uint32_t)((f - 1) & 1));
                    mbar_expect_tx(FULLB[s], 32768);
                    bulk_g2s(sb + SM_STG(s),         sa,  16384, FULLB[s]);
                    bulk_g2s(sb + SM_STG(s) + OFF_B, sbp, 16384, FULLB[s]);
                }
            }
            gcons++;
        }

        // publish next tile id + stage next bias
        __syncthreads();
        const int nt = *nextTS;
        int nb0 = 0, nn0 = 0, nmod = 0;
        const unsigned char *aN = aG, *bN = bG;
        if (nt < NT) {
            decode_tile(nt, aN, bN, nb0, nn0, nmod);
            const float* Bv = (nmod == 0) ? b_img : (nmod == 1) ? b_capt : b_dct;
            int n = nn0 + tid;
            biasNxt[tid] = Bv[((n & 7) << 6) + (n >> 3)];
        }

        // epilogue: bias + squash (8-col group == one n8 tile)
        const int t4 = lane & 3, g8 = lane >> 2;
        #pragma unroll
        for (int mt = 0; mt < 4; ++mt) {
            const int row0 = b0 + wm * 64 + mt * 16 + g8;
            #pragma unroll
            for (int ntj = 0; ntj < 8; ++ntj) {
                float* c = acc[mt][ntj];
                const int cl = wn * 64 + ntj * 8 + 2 * t4;
                const float bx = biasCur[cl], by = biasCur[cl + 1];
                float u0 = c[0] + bx, u1 = c[1] + by;
                float u2 = c[2] + bx, u3 = c[3] + by;
                float s0 = u0 * u0 + u1 * u1;
                float s1 = u2 * u2 + u3 * u3;
                s0 += __shfl_xor_sync(0xffffffffu, s0, 1);
                s0 += __shfl_xor_sync(0xffffffffu, s0, 2);
                s1 += __shfl_xor_sync(0xffffffffu, s1, 1);
                s1 += __shfl_xor_sync(0xffffffffu, s1, 2);
                float sc0 = s0 / ((1.0f + s0) * sqrtf(s0 + 1e-7f));
                float sc1 = s1 / ((1.0f + s1) * sqrtf(s1 + 1e-7f));
                float* p0 = out + (size_t)row0 * OUT_ROW + mod * 512 + n0 + cl;
                float* p1 = p0 + 8 * OUT_ROW;
                *(float2*)p0 = make_float2(u0 * sc0, u1 * sc0);
                *(float2*)p1 = make_float2(u2 * sc1, u3 * sc1);
            }
        }

        if (nt >= NT) break;
        __syncthreads();                 // epilogue bias reads done; nextTS reads done
        biasCur[tid] = biasNxt[tid];
        t = nt; aG = aN; bG = bN; b0 = nb0; n0 = nn0; mod = nmod;
    }
}

extern "C" void kernel_launch(void* const* d_in, const int* in_sizes, int n_in,
                              void* d_out, int out_size)
{
    const float* x_img  = (const float*)d_in[0];
    const float* x_capt = (const float*)d_in[1];
    const float* x_dct  = (const float*)d_in[2];
    const float* w_img  = (const float*)d_in[3];
    const float* b_img  = (const float*)d_in[4];
    const float* w_capt = (const float*)d_in[5];
    const float* b_capt = (const float*)d_in[6];
    const float* w_dct  = (const float*)d_in[7];
    const float* b_dct  = (const float*)d_in[8];
    float* out = (float*)d_out;

    cudaFuncSetAttribute(caps_gemm, cudaFuncAttributeMaxDynamicSharedMemorySize, SMEM_TOTAL);

    caps_conv<<<19008, 256>>>(x_img, x_capt, x_dct, w_img, w_capt, w_dct);

    caps_gemm<<<GRID_P, 128, SMEM_TOTAL>>>(b_img, b_capt, b_dct, out);
}